// round 15
// baseline (speedup 1.0000x reference)
#include <cuda_runtime.h>
#include <cuda_bf16.h>
#include <cuda_fp8.h>
#include <stdint.h>
#include <math.h>
#define BB 8
#define CCH 256
#define HW 12544
#define CHW 3211264
#define PP 196
#define TG 56
#define AA 3136
#define PSCALE 0.0078125f
#define GSCALE 0.0625f
typedef __nv_bfloat16 bf16;
typedef unsigned char u8;

__device__ u8    g_xn8[(size_t)BB*HW*CCH];
__device__ bf16  g_qT [(size_t)BB*HW*CCH];
__device__ bf16  g_kT [(size_t)BB*HW*CCH];
__device__ bf16  g_v  [(size_t)BB*HW*CCH];
__device__ bf16  g_hp [(size_t)BB*HW*CCH];
__device__ u8    g_hT8[(size_t)BB*HW*CCH];
__device__ u8    g_qp8[(size_t)BB*AA*CCH];
__device__ u8    g_kp8[(size_t)BB*AA*CCH];
__device__ u8    g_vp8[(size_t)BB*CCH*AA];
__device__ float g_hg [(size_t)BB*CCH*AA];
__device__ float g_attp4[(size_t)4*BB*PP*PP];
__device__ bf16  g_attpb[(size_t)BB*PP*PP];
__device__ float g_attg[(size_t)BB*AA*AA];
__device__ u8    g_ag8[(size_t)BB*AA*AA];
__device__ u8    g_wb8[(size_t)4*CCH*CCH];
__device__ double g_sum[BB], g_sq[BB];
__device__ float g_mean[BB], g_rstd[BB];

__device__ __forceinline__ uint32_t s2u(const void* p){
  uint32_t a; asm("{ .reg .u64 t; cvta.to.shared.u64 t, %1; cvt.u32.u64 %0, t; }":"=r"(a):"l"(p)); return a; }
__device__ __forceinline__ unsigned short bfr(float f){ bf16 h=__float2bfloat16(f); return *(unsigned short*)&h; }
__device__ __forceinline__ u8 f8(float f){ __nv_fp8_e4m3 h=__nv_fp8_e4m3(f); return *(u8*)&h; }
#define CPCOMMIT() asm volatile("cp.async.commit_group;":::"memory")
#define CPWAIT1() asm volatile("cp.async.wait_group 1;":::"memory")
#define CPWAIT0() asm volatile("cp.async.wait_group 0;":::"memory")

__device__ __forceinline__ void cp16(uint32_t db,const bf16* s,int pitch,int r0,int rmax,int tid){
  #pragma unroll
  for(int i=0;i<2;i++){
    int sl=tid+i*256,r=sl>>2,ch=sl&3,gr=r0+r; gr=gr>rmax?rmax:gr;
    asm volatile("cp.async.ca.shared.global [%0],[%1],16;"
      ::"r"(db+(uint32_t)(r*80+ch*16)),"l"(s+(size_t)gr*pitch+ch*8):"memory");
  } }
__device__ __forceinline__ void cp16b(uint32_t db,const u8* s,int pitchB,int r0,int rmax,int tid){
  #pragma unroll
  for(int i=0;i<2;i++){
    int sl=tid+i*256,r=sl>>2,ch=sl&3,gr=r0+r; gr=gr>rmax?rmax:gr;
    asm volatile("cp.async.ca.shared.global [%0],[%1],16;"
      ::"r"(db+(uint32_t)(r*80+ch*16)),"l"(s+(size_t)gr*pitchB+ch*16):"memory");
  } }
__device__ __forceinline__ void cp8(uint32_t db,const bf16* s,int pitch,int r0,int rmax,int k0,int kmax,int tid){
  #pragma unroll
  for(int i=0;i<4;i++){
    int sl=tid+i*256,r=sl>>3,ch=sl&7,gr=r0+r; gr=gr>rmax?rmax:gr;
    int gk=k0+ch*4;
    int bytes=(kmax-gk)*2; bytes=bytes<0?0:(bytes>8?8:bytes);
    int gkc=gk<kmax?gk:(kmax-1);
    asm volatile("cp.async.ca.shared.global [%0],[%1],8,%2;"
      ::"r"(db+(uint32_t)(r*80+ch*8)),"l"(s+(size_t)gr*pitch+gkc),"r"(bytes):"memory");
  } }

__device__ __forceinline__ void mma_tile(float (&c)[4][4][4],uint32_t aB,uint32_t bB,int w,int lane){
  int wm=(w&1)*64, wn=(w>>1)*32;
  #pragma unroll
  for(int ks=0;ks<2;ks++){
    uint32_t a[4][4],bv[4][2];
    #pragma unroll
    for(int mi=0;mi<4;mi++){
      uint32_t ad=aB+(wm+mi*16+(lane&15))*80+ks*32+(lane>>4)*16;
      asm volatile("ldmatrix.sync.aligned.m8n8.x4.shared.b16 {%0,%1,%2,%3},[%4];"
        :"=r"(a[mi][0]),"=r"(a[mi][1]),"=r"(a[mi][2]),"=r"(a[mi][3]):"r"(ad));
    }
    #pragma unroll
    for(int ni=0;ni<4;ni++){
      uint32_t bd=bB+(wn+ni*8+(lane&7))*80+ks*32+((lane>>3)&1)*16;
      asm volatile("ldmatrix.sync.aligned.m8n8.x2.shared.b16 {%0,%1},[%2];"
        :"=r"(bv[ni][0]),"=r"(bv[ni][1]):"r"(bd));
    }
    #pragma unroll
    for(int mi=0;mi<4;mi++)
      #pragma unroll
      for(int ni=0;ni<4;ni++)
        asm volatile("mma.sync.aligned.m16n8k16.row.col.f32.bf16.bf16.f32 {%0,%1,%2,%3},{%4,%5,%6,%7},{%8,%9},{%0,%1,%2,%3};"
          :"+f"(c[mi][ni][0]),"+f"(c[mi][ni][1]),"+f"(c[mi][ni][2]),"+f"(c[mi][ni][3])
          :"r"(a[mi][0]),"r"(a[mi][1]),"r"(a[mi][2]),"r"(a[mi][3]),"r"(bv[ni][0]),"r"(bv[ni][1]));
  } }

__device__ __forceinline__ void mma_f8(float (&c)[4][4][4],uint32_t aB,uint32_t bB,int w,int lane){
  int wm=(w&1)*64, wn=(w>>1)*32;
  #pragma unroll
  for(int ks=0;ks<2;ks++){
    uint32_t a[4][4],bv[4][2];
    #pragma unroll
    for(int mi=0;mi<4;mi++){
      uint32_t ad=aB+(wm+mi*16+(lane&15))*80+ks*32+(lane>>4)*16;
      asm volatile("ldmatrix.sync.aligned.m8n8.x4.shared.b16 {%0,%1,%2,%3},[%4];"
        :"=r"(a[mi][0]),"=r"(a[mi][1]),"=r"(a[mi][2]),"=r"(a[mi][3]):"r"(ad));
    }
    #pragma unroll
    for(int ni=0;ni<4;ni++){
      uint32_t bd=bB+(wn+ni*8+(lane&7))*80+ks*32+((lane>>3)&1)*16;
      asm volatile("ldmatrix.sync.aligned.m8n8.x2.shared.b16 {%0,%1},[%2];"
        :"=r"(bv[ni][0]),"=r"(bv[ni][1]):"r"(bd));
    }
    #pragma unroll
    for(int mi=0;mi<4;mi++)
      #pragma unroll
      for(int ni=0;ni<4;ni++)
        asm volatile("mma.sync.aligned.m16n8k32.row.col.f32.e4m3.e4m3.f32 {%0,%1,%2,%3},{%4,%5,%6,%7},{%8,%9},{%0,%1,%2,%3};"
          :"+f"(c[mi][ni][0]),"+f"(c[mi][ni][1]),"+f"(c[mi][ni][2]),"+f"(c[mi][ni][3])
          :"r"(a[mi][0]),"r"(a[mi][1]),"r"(a[mi][2]),"r"(a[mi][3]),"r"(bv[ni][0]),"r"(bv[ni][1]));
  } }

__device__ __forceinline__ void dump_chunk(float* Cs,int w,int lane,int j,float (&c)[4][4][4]){
  if((w>>1)==j){
    int wm=(w&1)*64;
    #pragma unroll
    for(int mi=0;mi<4;mi++)
      #pragma unroll
      for(int ni=0;ni<4;ni++){
        int r=wm+mi*16+(lane>>2), cc=ni*8+(lane&3)*2;
        Cs[r*33+cc]=c[mi][ni][0]; Cs[r*33+cc+1]=c[mi][ni][1];
        Cs[(r+8)*33+cc]=c[mi][ni][2]; Cs[(r+8)*33+cc+1]=c[mi][ni][3];
      }
  } }

#define GEMM_PRE \
  __shared__ __align__(16) char smch[40960]; \
  float* Cs=(float*)smch; \
  uint32_t smb=s2u(smch); \
  int t=threadIdx.x,w=t>>5,lane=t&31,m_=t&127,grp=t>>7; \
  float c[4][4][4]={};
#define ABUF(i) (smb+(uint32_t)(i)*20480u)
#define BBUF(i) (smb+(uint32_t)(i)*20480u+10240u)

__global__ void k_zero(){ int t=threadIdx.x; if(t<BB){ g_sum[t]=0.0; g_sq[t]=0.0; } }
__global__ void k_wcvt(const float* __restrict__ wq,const float* __restrict__ wk,
                       const float* __restrict__ wv,const float* __restrict__ wp){
  int i=blockIdx.x*256+threadIdx.x;
  g_wb8[i]=f8(wq[i]*16.f);
  g_wb8[65536+i]=f8(wk[i]*16.f);
  g_wb8[131072+i]=f8(wv[i]*16.f);
  g_wb8[196608+i]=f8(wp[i]*16.f); }
__global__ void k_gnstats(const float* __restrict__ x){
  int b=blockIdx.y; const float4* xb=(const float4*)(x+(size_t)b*CHW);
  float s=0.f,ss=0.f;
  for(int i=blockIdx.x*blockDim.x+threadIdx.x;i<CHW/4;i+=gridDim.x*blockDim.x){
    float4 v=xb[i]; s+=v.x+v.y+v.z+v.w; ss+=v.x*v.x+v.y*v.y+v.z*v.z+v.w*v.w; }
  __shared__ double sh[256],sh2[256];
  sh[threadIdx.x]=(double)s; sh2[threadIdx.x]=(double)ss; __syncthreads();
  for(int o=128;o>0;o>>=1){ if(threadIdx.x<o){ sh[threadIdx.x]+=sh[threadIdx.x+o]; sh2[threadIdx.x]+=sh2[threadIdx.x+o]; } __syncthreads(); }
  if(threadIdx.x==0){ atomicAdd(&g_sum[b],sh[0]); atomicAdd(&g_sq[b],sh2[0]); } }
__global__ void k_gnfin(){
  int b=threadIdx.x;
  if(b<BB){ double n=(double)CHW,mu=g_sum[b]/n,var=g_sq[b]/n-mu*mu;
    g_mean[b]=(float)mu; g_rstd[b]=(float)rsqrt(var+1e-5); } }

__global__ void __launch_bounds__(256) k_normT(const float* __restrict__ x,const float* __restrict__ gw,const float* __restrict__ gb){
  __shared__ bf16 sm[32][132];
  int b=blockIdx.z,c0=blockIdx.y*32,hw0=blockIdx.x*128,t=threadIdx.x;
  float mu=g_mean[b],rs=g_rstd[b];
  #pragma unroll
  for(int i=0;i<4;i++){
    int r=i*8+(t>>5),ch=t&31,c=c0+r;
    float sc=rs*gw[c],sh=gb[c]-mu*sc;
    float4 v=*(const float4*)(x+(size_t)b*CHW+(size_t)c*HW+hw0+ch*4);
    sm[r][ch*4+0]=__float2bfloat16(v.x*sc+sh); sm[r][ch*4+1]=__float2bfloat16(v.y*sc+sh);
    sm[r][ch*4+2]=__float2bfloat16(v.z*sc+sh); sm[r][ch*4+3]=__float2bfloat16(v.w*sc+sh);
  }
  __syncthreads();
  u8* dst=g_xn8+(size_t)b*HW*CCH;
  #pragma unroll
  for(int i=0;i<2;i++){
    int sl=t+i*256,j=sl>>2,part=sl&3; u8 tmp[8];
    #pragma unroll
    for(int e=0;e<8;e++) tmp[e]=f8(__bfloat162float(sm[part*8+e][j]));
    *(uint2*)(dst+(size_t)(hw0+j)*CCH+c0+part*8)=*(uint2*)tmp;
  } }

__global__ void __launch_bounds__(256) k_qkv_mm(const float* __restrict__ bq,
    const float* __restrict__ bk,const float* __restrict__ bv){
  GEMM_PRE
  int b=blockIdx.z,mb=blockIdx.y,n0=blockIdx.x*128,seg=mb>>1,o0=(mb&1)*128;
  const u8* W=g_wb8+(size_t)seg*65536;
  const float* Bi=seg==0?bq:(seg==1?bk:bv);
  const u8* X=g_xn8+(size_t)b*HW*CCH;
  cp16b(ABUF(0),W,CCH,o0,255,t); cp16b(BBUF(0),X,CCH,n0,HW-1,t); CPCOMMIT();
  for(int kt=0;kt<4;kt++){
    if(kt<3){ cp16b(ABUF((kt+1)&1),W+(kt+1)*64,CCH,o0,255,t);
              cp16b(BBUF((kt+1)&1),X+(kt+1)*64,CCH,n0,HW-1,t); CPCOMMIT(); CPWAIT1(); }
    else CPWAIT0();
    __syncthreads();
    mma_f8(c,ABUF(kt&1),BBUF(kt&1),w,lane);
    __syncthreads();
  }
  int o=o0+m_; float bias=Bi[o];
  for(int j=0;j<4;j++){
    __syncthreads(); dump_chunk(Cs,w,lane,j,c); __syncthreads();
    if(seg<2){
      bf16* dst=(seg?g_kT:g_qT)+(size_t)b*HW*CCH;
      #pragma unroll
      for(int e=0;e<16;e++){
        int n=n0+j*32+grp*16+e;
        dst[(size_t)n*CCH+o]=__float2bfloat16(Cs[m_*33+grp*16+e]*0.0625f+bias);
      }
    }else{
      bf16* dst=g_v+(size_t)b*HW*CCH+(size_t)o*HW;
      unsigned short buf[16];
      #pragma unroll
      for(int e=0;e<16;e++) buf[e]=bfr(Cs[m_*33+grp*16+e]*0.0625f+bias);
      *(uint4*)(dst+n0+j*32+grp*16)=*(uint4*)buf;
      *(uint4*)(dst+n0+j*32+grp*16+8)=*(uint4*)(buf+8);
    }
  } }

__global__ void __launch_bounds__(256) k_pscore_mm(){
  GEMM_PRE
  int z=blockIdx.z,b=z>>2,ks=z&3,m0=blockIdx.y*128,n0=blockIdx.x*128;
  const bf16* Q=g_qT+(size_t)b*HW*CCH;
  const bf16* K=g_kT+(size_t)b*HW*CCH;
  {
    cp16(ABUF(0),Q+(size_t)(ks*16)*PP*CCH,CCH,m0,PP-1,t);
    cp16(BBUF(0),K+(size_t)(ks*16)*PP*CCH,CCH,n0,PP-1,t); CPCOMMIT();
  }
  for(int it=0;it<128;it++){
    if(it<127){
      int s=ks*16+((it+1)>>3),kc=(it+1)&7;
      cp16(ABUF((it+1)&1),Q+(size_t)s*PP*CCH+kc*32,CCH,m0,PP-1,t);
      cp16(BBUF((it+1)&1),K+(size_t)s*PP*CCH+kc*32,CCH,n0,PP-1,t); CPCOMMIT(); CPWAIT1();
    } else CPWAIT0();
    __syncthreads();
    mma_tile(c,ABUF(it&1),BBUF(it&1),w,lane);
    __syncthreads();
  }
  int p=m0+m_;
  float* dst=g_attp4+((size_t)(ks*BB+b)*PP+(p<PP?p:0))*PP;
  for(int j=0;j<4;j++){
    __syncthreads(); dump_chunk(Cs,w,lane,j,c); __syncthreads();
    if(p<PP){
      #pragma unroll
      for(int e=0;e<16;e++){
        int q=n0+j*32+grp*16+e;
        if(q<PP) dst[q]=Cs[m_*33+grp*16+e]*PSCALE;
      }
    }
  } }

__global__ void k_psoftmax(){
  int p=blockIdx.x,b=blockIdx.y,t=threadIdx.x;
  float v=-1e30f;
  if(t<PP){ v=0.f;
    #pragma unroll
    for(int ks=0;ks<4;ks++) v+=g_attp4[((size_t)(ks*BB+b)*PP+p)*PP+t]; }
  __shared__ float sh[256];
  sh[t]=v; __syncthreads();
  for(int o=128;o;o>>=1){ if(t<o) sh[t]=fmaxf(sh[t],sh[t+o]); __syncthreads(); }
  float m=sh[0]; __syncthreads();
  float e=(t<PP)?__expf(v-m):0.f;
  sh[t]=e; __syncthreads();
  for(int o=128;o;o>>=1){ if(t<o) sh[t]+=sh[t+o]; __syncthreads(); }
  float inv=1.f/sh[0];
  if(t<PP) g_attpb[((size_t)b*PP+p)*PP+t]=__float2bfloat16(e*inv); }

__global__ void __launch_bounds__(256) k_ph_mm(){
  GEMM_PRE
  int b=blockIdx.z,m0=blockIdx.y*128,n0=blockIdx.x*128;
  const bf16* V=g_v+(size_t)b*HW*CCH;
  const bf16* A=g_attpb+(size_t)b*PP*PP;
  cp8(ABUF(0),V,PP,m0,16383,0,PP,t); cp8(BBUF(0),A,PP,n0,PP-1,0,PP,t); CPCOMMIT();
  for(int kt=0;kt<7;kt++){
    if(kt<6){ cp8(ABUF((kt+1)&1),V,PP,m0,16383,(kt+1)*32,PP,t);
              cp8(BBUF((kt+1)&1),A,PP,n0,PP-1,(kt+1)*32,PP,t); CPCOMMIT(); CPWAIT1(); }
    else CPWAIT0();
    __syncthreads();
    mma_tile(c,ABUF(kt&1),BBUF(kt&1),w,lane);
    __syncthreads();
  }
  int d=m0+m_;
  bf16* dst=g_hp+(size_t)b*HW*CCH+(size_t)d*PP;
  for(int j=0;j<4;j++){
    __syncthreads(); dump_chunk(Cs,w,lane,j,c); __syncthreads();
    #pragma unroll
    for(int e=0;e<16;e++){
      int p=n0+j*32+grp*16+e;
      if(p<PP) dst[p]=__float2bfloat16(Cs[m_*33+grp*16+e]);
    }
  } }

__global__ void k_pool_qk(){
  int a=blockIdx.x,b=blockIdx.y,c=threadIdx.x,y=a/TG,x=a%TG;
  size_t h00=(size_t)(2*y*112+2*x)*CCH+c;
  const bf16* Q=g_qT+(size_t)b*HW*CCH;
  const bf16* K=g_kT+(size_t)b*HW*CCH;
  float qv=0.25f*(__bfloat162float(Q[h00])+__bfloat162float(Q[h00+CCH])+__bfloat162float(Q[h00+112*CCH])+__bfloat162float(Q[h00+113*CCH]));
  float kv=0.25f*(__bfloat162float(K[h00])+__bfloat162float(K[h00+CCH])+__bfloat162float(K[h00+112*CCH])+__bfloat162float(K[h00+113*CCH]));
  g_qp8[((size_t)b*AA+a)*CCH+c]=f8(qv);
  g_kp8[((size_t)b*AA+a)*CCH+c]=f8(kv); }
__global__ void k_pool_v(){
  int c=blockIdx.x,b=blockIdx.y,t=threadIdx.x;
  const bf16* V=g_v+(size_t)b*HW*CCH+(size_t)c*HW;
  u8* dst=g_vp8+((size_t)b*CCH+c)*AA;
  for(int i=0;i<13;i++){
    int a=t+i*256;
    if(a<AA){
      int y=a/TG,x=a%TG,h00=2*y*112+2*x;
      float v=0.25f*(__bfloat162float(V[h00])+__bfloat162float(V[h00+1])+__bfloat162float(V[h00+112])+__bfloat162float(V[h00+113]));
      dst[a]=f8(v);
    }
  } }

__global__ void __launch_bounds__(256) k_gscore_mm(){
  GEMM_PRE
  int b=blockIdx.z,m0=blockIdx.y*128,n0=blockIdx.x*128;
  const u8* Q=g_qp8+(size_t)b*AA*CCH;
  const u8* K=g_kp8+(size_t)b*AA*CCH;
  cp16b(ABUF(0),Q,CCH,m0,AA-1,t); cp16b(BBUF(0),K,CCH,n0,AA-1,t); CPCOMMIT();
  for(int kt=0;kt<4;kt++){
    if(kt<3){ cp16b(ABUF((kt+1)&1),Q+(kt+1)*64,CCH,m0,AA-1,t);
              cp16b(BBUF((kt+1)&1),K+(kt+1)*64,CCH,n0,AA-1,t); CPCOMMIT(); CPWAIT1(); }
    else CPWAIT0();
    __syncthreads();
    mma_f8(c,ABUF(kt&1),BBUF(kt&1),w,lane);
    __syncthreads();
  }
  int p=m0+m_;
  float* dst=g_attg+((size_t)b*AA+(p<AA?p:0))*AA;
  for(int j=0;j<4;j++){
    __syncthreads(); dump_chunk(Cs,w,lane,j,c); __syncthreads();
    if(p<AA){
      #pragma unroll
      for(int e=0;e<16;e++){
        int q=n0+j*32+grp*16+e;
        if(q<AA) dst[q]=Cs[m_*33+grp*16+e]*GSCALE;
      }
    }
  } }

__global__ void k_gsoftmax(){
  size_t row=(size_t)blockIdx.y*AA+blockIdx.x;
  const float* src=g_attg+row*AA;
  u8* dst=g_ag8+row*AA;
  int t=threadIdx.x;
  float v[13],mx=-1e30f;
  #pragma unroll
  for(int i=0;i<13;i++){ int c=t+i*256; v[i]=(c<AA)?src[c]:-1e30f; mx=fmaxf(mx,v[i]); }
  __shared__ float sh[256];
  sh[t]=mx; __syncthreads();
  for(int o=128;o;o>>=1){ if(t<o) sh[t]=fmaxf(sh[t],sh[t+o]); __syncthreads(); }
  float m=sh[0]; __syncthreads();
  float s=0.f;
  #pragma unroll
  for(int i=0;i<13;i++){ int c=t+i*256; if(c<AA){ v[i]=__expf(v[i]-m); s+=v[i]; } }
  sh[t]=s; __syncthreads();
  for(int o=128;o;o>>=1){ if(t<o) sh[t]+=sh[t+o]; __syncthreads(); }
  float inv=256.f/sh[0];
  #pragma unroll
  for(int i=0;i<13;i++){ int c=t+i*256; if(c<AA) dst[c]=f8(v[i]*inv); } }

__global__ void __launch_bounds__(256) k_gh_mm(){
  GEMM_PRE
  int b=blockIdx.z,m0=blockIdx.y*128,n0=blockIdx.x*128;
  const u8* V=g_vp8+(size_t)b*CCH*AA;
  const u8* A=g_ag8+(size_t)b*AA*AA;
  cp16b(ABUF(0),V,AA,m0,CCH-1,t); cp16b(BBUF(0),A,AA,n0,AA-1,t); CPCOMMIT();
  for(int kt=0;kt<49;kt++){
    if(kt<48){ cp16b(ABUF((kt+1)&1),V+(kt+1)*64,AA,m0,CCH-1,t);
               cp16b(BBUF((kt+1)&1),A+(kt+1)*64,AA,n0,AA-1,t); CPCOMMIT(); CPWAIT1(); }
    else CPWAIT0();
    __syncthreads();
    mma_f8(c,ABUF(kt&1),BBUF(kt&1),w,lane);
    __syncthreads();
  }
  int cc=m0+m_;
  float* dst=g_hg+((size_t)b*CCH+cc)*AA;
  for(int j=0;j<4;j++){
    __syncthreads(); dump_chunk(Cs,w,lane,j,c); __syncthreads();
    #pragma unroll
    for(int e=0;e<16;e++){
      int a=n0+j*32+grp*16+e;
      if(a<AA) dst[a]=Cs[m_*33+grp*16+e]*0.00390625f;
    }
  } }

__global__ void __launch_bounds__(256) k_comb(){
  __shared__ bf16 sm[32][132];
  int b=blockIdx.z,c0=blockIdx.y*32,hw0=blockIdx.x*128,t=threadIdx.x;
  #pragma unroll
  for(int i=0;i<4;i++){
    int r=i*8+(t>>5),ch=t&31,c=c0+r;
    const bf16* hp=g_hp+(size_t)b*HW*CCH+(size_t)c*HW+hw0+ch*4;
    const float* hg=g_hg+((size_t)b*CCH+c)*AA;
    uint2 raw=*(const uint2*)hp; bf16 hpv[4]; *(uint2*)hpv=raw;
    #pragma unroll
    for(int e=0;e<4;e++){
      int hw=hw0+ch*4+e,yi=hw/112,xj=hw%112;
      float sy=yi*0.5f-0.25f; int y0=(int)floorf(sy); float fy=sy-(float)y0;
      int y0c=max(y0,0),y1c=min(y0+1,TG-1);
      float sx=xj*0.5f-0.25f; int x0=(int)floorf(sx); float fx=sx-(float)x0;
      int x0c=max(x0,0),x1c=min(x0+1,TG-1);
      float hv=(1.f-fy)*((1.f-fx)*hg[y0c*TG+x0c]+fx*hg[y0c*TG+x1c])+fy*((1.f-fx)*hg[y1c*TG+x0c]+fx*hg[y1c*TG+x1c]);
      sm[r][ch*4+e]=__float2bfloat16(0.75f*__bfloat162float(hpv[e])+0.25f*hv);
    }
  }
  __syncthreads();
  u8* dst=g_hT8+(size_t)b*HW*CCH;
  #pragma unroll
  for(int i=0;i<2;i++){
    int sl=t+i*256,j=sl>>2,part=sl&3; u8 tmp[8];
    #pragma unroll
    for(int e=0;e<8;e++) tmp[e]=f8(__bfloat162float(sm[part*8+e][j])*32.f);
    *(uint2*)(dst+(size_t)(hw0+j)*CCH+c0+part*8)=*(uint2*)tmp;
  } }

__global__ void __launch_bounds__(256) k_proj_mm(const float* __restrict__ x,float* __restrict__ out){
  GEMM_PRE
  int b=blockIdx.z,o0=blockIdx.y*128,n0=blockIdx.x*128;
  const u8* W=g_wb8+(size_t)3*65536;
  const u8* Hh=g_hT8+(size_t)b*HW*CCH;
  cp16b(ABUF(0),W,CCH,o0,255,t); cp16b(BBUF(0),Hh,CCH,n0,HW-1,t); CPCOMMIT();
  for(int kt=0;kt<4;kt++){
    if(kt<3){ cp16b(ABUF((kt+1)&1),W+(kt+1)*64,CCH,o0,255,t);
              cp16b(BBUF((kt+1)&1),Hh+(kt+1)*64,CCH,n0,HW-1,t); CPCOMMIT(); CPWAIT1(); }
    else CPWAIT0();
    __syncthreads();
    mma_f8(c,ABUF(kt&1),BBUF(kt&1),w,lane);
    __syncthreads();
  }
  int o=o0+m_;
  size_t base=(size_t)b*CHW+(size_t)o*HW;
  for(int j=0;j<4;j++){
    __syncthreads(); dump_chunk(Cs,w,lane,j,c); __syncthreads();
    #pragma unroll
    for(int e=0;e<16;e++){
      size_t off=base+n0+j*32+grp*16+e;
      out[off]=Cs[m_*33+grp*16+e]*0.001953125f+x[off];
    }
  } }

extern "C" void kernel_launch(void* const* d_in,const int* in_sizes,int n_in,void* d_out,int out_size){
  const float* x =(const float*)d_in[0];
  const float* gw=(const float*)d_in[1];
  const float* gb=(const float*)d_in[2];
  const float* wq=(const float*)d_in[3];
  const float* bq=(const float*)d_in[4];
  const float* wk=(const float*)d_in[5];
  const float* bk=(const float*)d_in[6];
  const float* wv=(const float*)d_in[7];
  const float* bv=(const float*)d_in[8];
  const float* wp=(const float*)d_in[9];
  float* out=(float*)d_out;
  k_zero<<<1,32>>>();
  k_wcvt<<<256,256>>>(wq,wk,wv,wp);
  k_gnstats<<<dim3(64,8),256>>>(x);
  k_gnfin<<<1,32>>>();
  k_normT<<<dim3(98,8,8),256>>>(x,gw,gb);
  k_qkv_mm<<<dim3(98,6,8),256>>>(bq,bk,bv);
  k_pscore_mm<<<dim3(2,2,32),256>>>();
  k_psoftmax<<<dim3(PP,BB),256>>>();
  k_ph_mm<<<dim3(2,128,8),256>>>();
  k_pool_qk<<<dim3(AA,BB),256>>>();
  k_pool_v<<<dim3(CCH,BB),256>>>();
  k_gscore_mm<<<dim3(25,25,8),256>>>();
  k_gsoftmax<<<dim3(AA,BB),256>>>();
  k_gh_mm<<<dim3(25,2,8),256>>>();
  k_comb<<<dim3(98,8,8),256>>>();
  k_proj_mm<<<dim3(98,2,8),256>>>(x,out);
}